// round 3
// baseline (speedup 1.0000x reference)
#include <cuda_runtime.h>

// ---------------- problem constants ----------------
#define BATCH 128
#define CCH   3
#define IMH   224
#define IMW   224
#define GG    32
#define HGI   1024
#define HLI   256
#define DIN   9216      // 3 scales * 3 ch * 32*32
#define NOUT  1280      // HG + HL

// ---------------- GEMM tiling ----------------
#define BM 64
#define BN 128
#define BK 16
#define ASTRIDE (BM + 4)
#define WSTRIDE (BN + 4)

#define KS1 18
#define KC1 (DIN / KS1)   // 512
#define KS2 10
#define KC2 128           // 8 splits cover w3 (1024), 2 cover w4 (256)

// ---------------- scratch (static device memory; no allocs) ----------------
__device__ float g_phi  [BATCH * DIN];
__device__ float g_part1[KS1 * BATCH * HGI];
__device__ float g_s1   [BATCH * HGI];
__device__ float g_lout [BATCH * HLI];
__device__ float g_part2[KS2 * BATCH * NOUT];

// ---------------- packed fp32x2 helpers ----------------
__device__ __forceinline__ unsigned long long fma2(unsigned long long a,
                                                   unsigned long long b,
                                                   unsigned long long c) {
    unsigned long long d;
    asm("fma.rn.f32x2 %0, %1, %2, %3;" : "=l"(d) : "l"(a), "l"(b), "l"(c));
    return d;
}
__device__ __forceinline__ unsigned long long dup2(float x) {
    unsigned long long d;
    asm("mov.b64 %0, {%1, %1};" : "=l"(d) : "f"(x));
    return d;
}

// glimpse start index, replicating jax: (0.5f*((l+1.0f)*224.0f)) -> int32 trunc
__device__ __forceinline__ int start_idx(float lv) {
    float t = (lv + 1.0f) * 224.0f;
    return (int)(0.5f * t);
}

// ---------------- patch extraction (one scale per instantiation) ----------------
template <int SCALE>
__global__ void extract_kernel(const float* __restrict__ x,
                               const float* __restrict__ l) {
    constexpr int F   = 1 << SCALE;            // 1, 2, 4
    constexpr int PAD = (GG << SCALE) >> 1;    // 16, 32, 64
    const int b = blockIdx.x;
    const int sx = start_idx(l[b * 2 + 0]);
    const int sy = start_idx(l[b * 2 + 1]);
    const float* xb = x + (size_t)b * CCH * IMH * IMW;
    const float invf = 1.0f / (float)(F * F);

    for (int idx = threadIdx.x; idx < CCH * GG * GG; idx += blockDim.x) {
        const int col = idx & 31;
        const int r   = (idx >> 5) & 31;
        const int c   = idx >> 10;
        const int row0 = sy - PAD + r * F;
        const int col0 = sx - PAD + col * F;
        float s = 0.0f;
#pragma unroll
        for (int dy = 0; dy < F; dy++) {
            const int rr = row0 + dy;
            if (rr < 0 || rr >= IMH) continue;
            const float* xr = xb + ((size_t)c * IMH + rr) * IMW;
#pragma unroll
            for (int dx = 0; dx < F; dx++) {
                const int cc = col0 + dx;
                if (cc >= 0 && cc < IMW) s += xr[cc];
            }
        }
        g_phi[(size_t)b * DIN + ((SCALE * CCH + c) * GG + r) * GG + col] = s * invf;
    }
}

// ---------------- mask (union == largest concentric rect, clipped) ----------------
__global__ void mask_kernel(const float* __restrict__ l, float* __restrict__ om) {
    const int b = blockIdx.y;
    const int p = blockIdx.x * blockDim.x + threadIdx.x;
    if (p >= IMH * IMW) return;
    const int sx = start_idx(l[b * 2 + 0]);
    const int sy = start_idx(l[b * 2 + 1]);
    const int r = p / IMW;
    const int c = p % IMW;
    const bool in = (r >= sy - 64) && (r < sy + 64) && (c >= sx - 64) && (c < sx + 64);
    om[(size_t)b * IMH * IMW + p] = in ? 1.0f : 0.0f;
}

// ---------------- l_out = relu(l @ w2.T + b2) ----------------
__global__ void lout_kernel(const float* __restrict__ l,
                            const float* __restrict__ w2,
                            const float* __restrict__ b2) {
    const int i = blockIdx.x * blockDim.x + threadIdx.x;   // < 128*256
    const int m = i >> 8;
    const int j = i & 255;
    float v = fmaf(l[m * 2 + 0], w2[j * 2 + 0],
              fmaf(l[m * 2 + 1], w2[j * 2 + 1], b2[j]));
    g_lout[i] = fmaxf(v, 0.0f);
}

// ---------------- split-K fp32x2 GEMM tile (C[m,n] = sum_k A[m,k]*W[n,k]) ----------------
__device__ __forceinline__ void gemm_tile(const float* __restrict__ A, int ldA,
                                          const float* __restrict__ W, int ldW,
                                          int bm, int bn, int kbeg, int kcount,
                                          float* __restrict__ outP, int ldOut) {
    __shared__ __align__(16) float As[BK][ASTRIDE];
    __shared__ __align__(16) float Ws[BK][WSTRIDE];
    const int tid = threadIdx.x;          // 256 threads
    const int tx = tid & 15;              // -> 8 cols each
    const int ty = tid >> 4;              // -> 4 rows each

    unsigned long long acc[4][4];
#pragma unroll
    for (int i = 0; i < 4; i++)
#pragma unroll
        for (int j = 0; j < 4; j++) acc[i][j] = 0ull;

    const int lrow = tid >> 2;            // 0..63
    const int lkq  = (tid & 3) * 4;       // 0,4,8,12

    for (int kt = 0; kt < kcount; kt += BK) {
        const int kb = kbeg + kt;
        // A tile: 64 rows x 16 k (one float4/thread)
        {
            float4 v = *(const float4*)&A[(size_t)(bm + lrow) * ldA + kb + lkq];
            As[lkq + 0][lrow] = v.x; As[lkq + 1][lrow] = v.y;
            As[lkq + 2][lrow] = v.z; As[lkq + 3][lrow] = v.w;
        }
        // W tile: 128 rows x 16 k (two float4/thread)
#pragma unroll
        for (int h = 0; h < 2; h++) {
            const int row = lrow + h * 64;
            float4 v = *(const float4*)&W[(size_t)(bn + row) * ldW + kb + lkq];
            Ws[lkq + 0][row] = v.x; Ws[lkq + 1][row] = v.y;
            Ws[lkq + 2][row] = v.z; Ws[lkq + 3][row] = v.w;
        }
        __syncthreads();
#pragma unroll
        for (int kk = 0; kk < BK; kk++) {
            float4 a4 = *(const float4*)&As[kk][ty * 4];
            ulonglong2 w01 = *(const ulonglong2*)&Ws[kk][tx * 8];
            ulonglong2 w23 = *(const ulonglong2*)&Ws[kk][tx * 8 + 4];
            unsigned long long ad;
            ad = dup2(a4.x);
            acc[0][0] = fma2(ad, w01.x, acc[0][0]); acc[0][1] = fma2(ad, w01.y, acc[0][1]);
            acc[0][2] = fma2(ad, w23.x, acc[0][2]); acc[0][3] = fma2(ad, w23.y, acc[0][3]);
            ad = dup2(a4.y);
            acc[1][0] = fma2(ad, w01.x, acc[1][0]); acc[1][1] = fma2(ad, w01.y, acc[1][1]);
            acc[1][2] = fma2(ad, w23.x, acc[1][2]); acc[1][3] = fma2(ad, w23.y, acc[1][3]);
            ad = dup2(a4.z);
            acc[2][0] = fma2(ad, w01.x, acc[2][0]); acc[2][1] = fma2(ad, w01.y, acc[2][1]);
            acc[2][2] = fma2(ad, w23.x, acc[2][2]); acc[2][3] = fma2(ad, w23.y, acc[2][3]);
            ad = dup2(a4.w);
            acc[3][0] = fma2(ad, w01.x, acc[3][0]); acc[3][1] = fma2(ad, w01.y, acc[3][1]);
            acc[3][2] = fma2(ad, w23.x, acc[3][2]); acc[3][3] = fma2(ad, w23.y, acc[3][3]);
        }
        __syncthreads();
    }

#pragma unroll
    for (int i = 0; i < 4; i++) {
        const int m = bm + ty * 4 + i;
        ulonglong2* q = (ulonglong2*)&outP[(size_t)m * ldOut + bn + tx * 8];
        q[0] = make_ulonglong2(acc[i][0], acc[i][1]);
        q[1] = make_ulonglong2(acc[i][2], acc[i][3]);
    }
}

__global__ void __launch_bounds__(256) gemm1_kernel(const float* __restrict__ w1) {
    const int bn = blockIdx.x * BN;
    const int bm = blockIdx.y * BM;
    const int ks = blockIdx.z;
    gemm_tile(g_phi, DIN, w1, DIN, bm, bn, ks * KC1, KC1,
              g_part1 + (size_t)ks * BATCH * HGI, HGI);
}

__global__ void reduce1_kernel(const float* __restrict__ b1) {
    const int i = blockIdx.x * blockDim.x + threadIdx.x;   // < 128*1024
    float s = b1[i & (HGI - 1)];
#pragma unroll
    for (int p = 0; p < KS1; p++) s += g_part1[(size_t)p * BATCH * HGI + i];
    g_s1[i] = fmaxf(s, 0.0f);
}

__global__ void __launch_bounds__(256) gemm2_kernel(const float* __restrict__ w3,
                                                    const float* __restrict__ w4) {
    const int bn = blockIdx.x * BN;
    const int bm = blockIdx.y * BM;
    const int ks = blockIdx.z;
    const float* A; const float* W; int ld, kb;
    if (ks < 8) { A = g_s1;  W = w3; ld = HGI; kb = ks * KC2; }
    else        { A = g_lout; W = w4; ld = HLI; kb = (ks - 8) * KC2; }
    gemm_tile(A, ld, W, ld, bm, bn, kb, KC2,
              g_part2 + (size_t)ks * BATCH * NOUT, NOUT);
}

__global__ void reduce2_kernel(const float* __restrict__ b3,
                               const float* __restrict__ b4,
                               float* __restrict__ out) {
    const int i = blockIdx.x * blockDim.x + threadIdx.x;   // < 128*1280
    const int n = i % NOUT;
    float s = b3[n] + b4[n];
#pragma unroll
    for (int p = 0; p < KS2; p++) s += g_part2[(size_t)p * BATCH * NOUT + i];
    out[i] = fmaxf(s, 0.0f);
}

// ---------------- launch ----------------
extern "C" void kernel_launch(void* const* d_in, const int* in_sizes, int n_in,
                              void* d_out, int out_size) {
    const float* x  = (const float*)d_in[0];
    const float* l  = (const float*)d_in[1];
    const float* w1 = (const float*)d_in[2];
    const float* b1 = (const float*)d_in[3];
    const float* w2 = (const float*)d_in[4];
    const float* b2 = (const float*)d_in[5];
    const float* w3 = (const float*)d_in[6];
    const float* b3 = (const float*)d_in[7];
    const float* w4 = (const float*)d_in[8];
    const float* b4 = (const float*)d_in[9];
    float* out = (float*)d_out;

    // outputs: g_t [128,1280] then mask [128, 224*224]
    extract_kernel<0><<<BATCH, 256>>>(x, l);
    extract_kernel<1><<<BATCH, 256>>>(x, l);
    extract_kernel<2><<<BATCH, 256>>>(x, l);
    mask_kernel<<<dim3((IMH * IMW) / 256, BATCH), 256>>>(l, out + BATCH * NOUT);
    lout_kernel<<<(BATCH * HLI) / 256, 256>>>(l, w2, b2);
    gemm1_kernel<<<dim3(HGI / BN, BATCH / BM, KS1), 256>>>(w1);
    reduce1_kernel<<<(BATCH * HGI) / 256, 256>>>(b1);
    gemm2_kernel<<<dim3(NOUT / BN, BATCH / BM, KS2), 256>>>(w3, w4);
    reduce2_kernel<<<(BATCH * NOUT) / 256, 256>>>(b3, b4, out);
}

// round 5
// speedup vs baseline: 2.4554x; 2.4554x over previous
#include <cuda_runtime.h>
#include <cuda_bf16.h>

// ---------------- problem constants ----------------
#define BATCH 128
#define CCH   3
#define IMH   224
#define IMW   224
#define GG    32
#define HGI   1024
#define HLI   256
#define DIN   9216
#define NOUT  1280

// ---------------- GEMM (mma.sync bf16x3) config ----------------
#define NT    64              // N tile per CTA
#define KSTG  32              // K per stage
#define GT    256             // threads (8 warps: 4 m x 2 n)
#define KS1   9
#define KSLICE1 (DIN / KS1)   // 1024
#define NCH1  (KSLICE1 / KSTG) // 32
#define KS2   5

// SMEM stage layout (bf16, row stride 40 elems = 80 bytes)
#define RS      80
#define OFF_AHI 0
#define OFF_ALO 10240
#define OFF_WHI 20480
#define OFF_WLO 25600
#define STG_BYTES 30720
#define SMEM_DYN (2 * STG_BYTES)   // 61440

// ---------------- scratch ----------------
__device__ float g_phi  [BATCH * DIN];
__device__ float g_part1[KS1 * BATCH * HGI];
__device__ float g_s1   [BATCH * HGI];
__device__ float g_lout [BATCH * HLI];
__device__ float g_part2[KS2 * BATCH * NOUT];

// ---------------- PTX helpers (base-target only) ----------------
__device__ __forceinline__ unsigned smem_u32(const void* p) {
    unsigned a;
    asm("{ .reg .u64 t; cvta.to.shared.u64 t, %1; cvt.u32.u64 %0, t; }" : "=r"(a) : "l"(p));
    return a;
}
__device__ __forceinline__ void ldsm_x4(unsigned& r0, unsigned& r1, unsigned& r2,
                                        unsigned& r3, unsigned addr) {
    asm volatile("ldmatrix.sync.aligned.m8n8.x4.shared.b16 {%0,%1,%2,%3}, [%4];"
                 : "=r"(r0), "=r"(r1), "=r"(r2), "=r"(r3) : "r"(addr));
}
__device__ __forceinline__ void mma_bf16(float* c, const unsigned* a, const unsigned* b) {
    asm volatile("mma.sync.aligned.m16n8k16.row.col.f32.bf16.bf16.f32 "
                 "{%0,%1,%2,%3}, {%4,%5,%6,%7}, {%8,%9}, {%0,%1,%2,%3};"
                 : "+f"(c[0]), "+f"(c[1]), "+f"(c[2]), "+f"(c[3])
                 : "r"(a[0]), "r"(a[1]), "r"(a[2]), "r"(a[3]), "r"(b[0]), "r"(b[1]));
}

// fp32 -> bf16 hi + bf16 residual (lo), 4 at a time
__device__ __forceinline__ void cvt4(float4 v, uint2& hi, uint2& lo) {
    __nv_bfloat162 h0 = __floats2bfloat162_rn(v.x, v.y);
    __nv_bfloat162 h1 = __floats2bfloat162_rn(v.z, v.w);
    float r0 = v.x - __bfloat162float(h0.x);
    float r1 = v.y - __bfloat162float(h0.y);
    float r2 = v.z - __bfloat162float(h1.x);
    float r3 = v.w - __bfloat162float(h1.y);
    __nv_bfloat162 l0 = __floats2bfloat162_rn(r0, r1);
    __nv_bfloat162 l1 = __floats2bfloat162_rn(r2, r3);
    hi = make_uint2(*(unsigned*)&h0, *(unsigned*)&h1);
    lo = make_uint2(*(unsigned*)&l0, *(unsigned*)&l1);
}

// ---------------- split-K bf16x3 mma.sync GEMM body ----------------
// outP[128, NT @ bn] = A[128, kbeg:kbeg+nch*32] @ W[bn:bn+NT, same]^T
__device__ __forceinline__ void gemm_body(const float* __restrict__ A, int ldA,
                                          const float* __restrict__ W, int ldW,
                                          float* __restrict__ outP, int ldOut,
                                          int bn, int kbeg, int nch) {
    extern __shared__ char smem[];
    const unsigned sb = smem_u32(smem);
    const int tid  = threadIdx.x;
    const int wid  = tid >> 5;
    const int lane = tid & 31;
    const int wm = (wid & 3) * 32;      // warp m offset
    const int wn = (wid >> 2) * 32;     // warp n offset

    float4 pa[4];
    float4 pw[2];

    // prefetch stage c from GMEM into registers (coalesced float4)
    auto ldg_stage = [&](int c) {
        const float* Ab = A + kbeg + c * KSTG;
#pragma unroll
        for (int j = 0; j < 4; j++) {
            int f4 = j * 256 + tid;
            pa[j] = *(const float4*)(Ab + (size_t)(f4 >> 3) * ldA + (f4 & 7) * 4);
        }
        const float* Wb = W + (size_t)bn * ldW + kbeg + c * KSTG;
#pragma unroll
        for (int j = 0; j < 2; j++) {
            int f4 = j * 256 + tid;
            pw[j] = *(const float4*)(Wb + (size_t)(f4 >> 3) * ldW + (f4 & 7) * 4);
        }
    };

    // convert + store registers into SMEM stage s
    auto sts_stage = [&](int s) {
        char* st = smem + s * STG_BYTES;
#pragma unroll
        for (int j = 0; j < 4; j++) {
            int f4 = j * 256 + tid;
            int off = (f4 >> 3) * RS + (f4 & 7) * 8;
            uint2 hi, lo;
            cvt4(pa[j], hi, lo);
            *(uint2*)(st + OFF_AHI + off) = hi;
            *(uint2*)(st + OFF_ALO + off) = lo;
        }
#pragma unroll
        for (int j = 0; j < 2; j++) {
            int f4 = j * 256 + tid;
            int off = (f4 >> 3) * RS + (f4 & 7) * 8;
            uint2 hi, lo;
            cvt4(pw[j], hi, lo);
            *(uint2*)(st + OFF_WHI + off) = hi;
            *(uint2*)(st + OFF_WLO + off) = lo;
        }
    };

    float acc[2][4][4];
#pragma unroll
    for (int i = 0; i < 2; i++)
#pragma unroll
        for (int j = 0; j < 4; j++)
#pragma unroll
            for (int k = 0; k < 4; k++) acc[i][j][k] = 0.0f;

    ldg_stage(0);
    sts_stage(0);
    if (nch > 1) ldg_stage(1);
    __syncthreads();

    for (int c = 0; c < nch; c++) {
        const unsigned base = sb + (unsigned)(c & 1) * STG_BYTES;
#pragma unroll
        for (int kk = 0; kk < KSTG; kk += 16) {
            unsigned ahi[2][4], alo[2][4], bhi[4][2], blo[4][2];
            // A fragments (16x16 per ldmatrix.x4)
#pragma unroll
            for (int mb = 0; mb < 2; mb++) {
                unsigned r = wm + mb * 16 + (lane & 15);
                unsigned ko = kk + ((lane & 16) ? 8 : 0);
                unsigned ad = base + r * RS + ko * 2;
                ldsm_x4(ahi[mb][0], ahi[mb][1], ahi[mb][2], ahi[mb][3], ad + OFF_AHI);
                ldsm_x4(alo[mb][0], alo[mb][1], alo[mb][2], alo[mb][3], ad + OFF_ALO);
            }
            // B fragments: each x4 covers two n-blocks of 8
#pragma unroll
            for (int p = 0; p < 2; p++) {
                unsigned m = lane >> 3;
                unsigned r = wn + p * 16 + ((m >= 2) ? 8 : 0) + (lane & 7);
                unsigned ko = kk + ((m & 1) ? 8 : 0);
                unsigned ad = base + r * RS + ko * 2;
                ldsm_x4(bhi[p * 2][0], bhi[p * 2][1], bhi[p * 2 + 1][0], bhi[p * 2 + 1][1],
                        ad + OFF_WHI);
                ldsm_x4(blo[p * 2][0], blo[p * 2][1], blo[p * 2 + 1][0], blo[p * 2 + 1][1],
                        ad + OFF_WLO);
            }
#pragma unroll
            for (int mb = 0; mb < 2; mb++)
#pragma unroll
                for (int nb = 0; nb < 4; nb++) {
                    mma_bf16(acc[mb][nb], ahi[mb], bhi[nb]);
                    mma_bf16(acc[mb][nb], ahi[mb], blo[nb]);
                    mma_bf16(acc[mb][nb], alo[mb], bhi[nb]);
                }
        }
        if (c + 1 < nch) {
            sts_stage((c + 1) & 1);
            if (c + 2 < nch) ldg_stage(c + 2);
            __syncthreads();
        }
    }

    // epilogue: write partials
#pragma unroll
    for (int mb = 0; mb < 2; mb++) {
        const int row = wm + mb * 16 + (lane >> 2);
#pragma unroll
        for (int nb = 0; nb < 4; nb++) {
            const int col = bn + wn + nb * 8 + (lane & 3) * 2;
            float* o = outP + (size_t)row * ldOut + col;
            *(float2*)o = make_float2(acc[mb][nb][0], acc[mb][nb][1]);
            *(float2*)(o + 8 * (size_t)ldOut) = make_float2(acc[mb][nb][2], acc[mb][nb][3]);
        }
    }
}

__global__ void __launch_bounds__(GT, 1) gemm1_mm(const float* __restrict__ w1) {
    gemm_body(g_phi, DIN, w1, DIN,
              g_part1 + (size_t)blockIdx.y * BATCH * HGI, HGI,
              blockIdx.x * NT, blockIdx.y * KSLICE1, NCH1);
}

__global__ void __launch_bounds__(GT, 1) gemm2_mm(const float* __restrict__ w3,
                                                  const float* __restrict__ w4) {
    const int z = blockIdx.y;
    const float* A; const float* W; int ld, kb;
    if (z < 4) { A = g_s1;   W = w3; ld = HGI; kb = z * 256; }
    else       { A = g_lout; W = w4; ld = HLI; kb = 0; }
    gemm_body(A, ld, W, ld,
              g_part2 + (size_t)z * BATCH * NOUT, NOUT,
              blockIdx.x * NT, kb, 256 / KSTG);
}

// ---------------- glimpse start index ----------------
__device__ __forceinline__ int start_idx(float lv) {
    return (int)(0.5f * ((lv + 1.0f) * 224.0f));
}

// ---------------- patch extraction (all scales, one launch) ----------------
template <int SCALE>
__device__ __forceinline__ void extract_body(const float* __restrict__ x,
                                             const float* __restrict__ l) {
    constexpr int F   = 1 << SCALE;
    constexpr int PAD = (GG << SCALE) >> 1;
    const int b = blockIdx.x;
    const int sx = start_idx(l[b * 2 + 0]);
    const int sy = start_idx(l[b * 2 + 1]);
    const float* xb = x + (size_t)b * CCH * IMH * IMW;
    const float invf = 1.0f / (float)(F * F);

    for (int idx = threadIdx.x; idx < CCH * GG * GG; idx += blockDim.x) {
        const int col = idx & 31;
        const int r   = (idx >> 5) & 31;
        const int c   = idx >> 10;
        const int row0 = sy - PAD + r * F;
        const int col0 = sx - PAD + col * F;
        float s = 0.0f;
#pragma unroll
        for (int dy = 0; dy < F; dy++) {
            const int rr = row0 + dy;
            if (rr < 0 || rr >= IMH) continue;
            const float* xr = xb + ((size_t)c * IMH + rr) * IMW;
#pragma unroll
            for (int dx = 0; dx < F; dx++) {
                const int cc = col0 + dx;
                if (cc >= 0 && cc < IMW) s += xr[cc];
            }
        }
        g_phi[(size_t)b * DIN + ((SCALE * CCH + c) * GG + r) * GG + col] = s * invf;
    }
}

__global__ void extract_all(const float* __restrict__ x, const float* __restrict__ l) {
    switch (blockIdx.y) {
        case 0: extract_body<0>(x, l); break;
        case 1: extract_body<1>(x, l); break;
        default: extract_body<2>(x, l); break;
    }
}

// ---------------- mask (union == largest concentric rect), float4 ----------------
__global__ void mask_kernel(const float* __restrict__ l, float* __restrict__ om) {
    const int b = blockIdx.y;
    const int q = blockIdx.x * blockDim.x + threadIdx.x;   // < 12544
    const int sx = start_idx(l[b * 2 + 0]);
    const int sy = start_idx(l[b * 2 + 1]);
    const int r  = q / 56;
    const int c0 = (q - r * 56) * 4;
    const bool iny = (r >= sy - 64) && (r < sy + 64);
    float4 v;
    v.x = (iny && c0 + 0 >= sx - 64 && c0 + 0 < sx + 64) ? 1.0f : 0.0f;
    v.y = (iny && c0 + 1 >= sx - 64 && c0 + 1 < sx + 64) ? 1.0f : 0.0f;
    v.z = (iny && c0 + 2 >= sx - 64 && c0 + 2 < sx + 64) ? 1.0f : 0.0f;
    v.w = (iny && c0 + 3 >= sx - 64 && c0 + 3 < sx + 64) ? 1.0f : 0.0f;
    ((float4*)(om + (size_t)b * IMH * IMW))[q] = v;
}

// ---------------- l_out = relu(l @ w2.T + b2) ----------------
__global__ void lout_kernel(const float* __restrict__ l,
                            const float* __restrict__ w2,
                            const float* __restrict__ b2) {
    const int i = blockIdx.x * blockDim.x + threadIdx.x;
    const int m = i >> 8;
    const int j = i & 255;
    float v = fmaf(l[m * 2 + 0], w2[j * 2 + 0],
              fmaf(l[m * 2 + 1], w2[j * 2 + 1], b2[j]));
    g_lout[i] = fmaxf(v, 0.0f);
}

// ---------------- reductions (bias + relu), float4 ----------------
__global__ void reduce1_kernel(const float* __restrict__ b1) {
    const int i4 = blockIdx.x * blockDim.x + threadIdx.x;  // < 32768
    float4 s = ((const float4*)g_part1)[i4];
#pragma unroll
    for (int p = 1; p < KS1; p++) {
        float4 v = ((const float4*)(g_part1 + (size_t)p * BATCH * HGI))[i4];
        s.x += v.x; s.y += v.y; s.z += v.z; s.w += v.w;
    }
    float4 bb = ((const float4*)b1)[i4 & 255];
    s.x = fmaxf(s.x + bb.x, 0.0f); s.y = fmaxf(s.y + bb.y, 0.0f);
    s.z = fmaxf(s.z + bb.z, 0.0f); s.w = fmaxf(s.w + bb.w, 0.0f);
    ((float4*)g_s1)[i4] = s;
}

__global__ void reduce2_kernel(const float* __restrict__ b3,
                               const float* __restrict__ b4,
                               float* __restrict__ out) {
    const int i4 = blockIdx.x * blockDim.x + threadIdx.x;  // < 40960
    float4 s = ((const float4*)g_part2)[i4];
#pragma unroll
    for (int p = 1; p < KS2; p++) {
        float4 v = ((const float4*)(g_part2 + (size_t)p * BATCH * NOUT))[i4];
        s.x += v.x; s.y += v.y; s.z += v.z; s.w += v.w;
    }
    const int n4 = i4 % (NOUT / 4);
    float4 t3 = ((const float4*)b3)[n4];
    float4 t4 = ((const float4*)b4)[n4];
    s.x = fmaxf(s.x + t3.x + t4.x, 0.0f); s.y = fmaxf(s.y + t3.y + t4.y, 0.0f);
    s.z = fmaxf(s.z + t3.z + t4.z, 0.0f); s.w = fmaxf(s.w + t3.w + t4.w, 0.0f);
    ((float4*)out)[i4] = s;
}

// ---------------- launch ----------------
extern "C" void kernel_launch(void* const* d_in, const int* in_sizes, int n_in,
                              void* d_out, int out_size) {
    const float* x  = (const float*)d_in[0];
    const float* l  = (const float*)d_in[1];
    const float* w1 = (const float*)d_in[2];
    const float* b1 = (const float*)d_in[3];
    const float* w2 = (const float*)d_in[4];
    const float* b2 = (const float*)d_in[5];
    const float* w3 = (const float*)d_in[6];
    const float* b3 = (const float*)d_in[7];
    const float* w4 = (const float*)d_in[8];
    const float* b4 = (const float*)d_in[9];
    float* out = (float*)d_out;

    cudaFuncSetAttribute(gemm1_mm, cudaFuncAttributeMaxDynamicSharedMemorySize, SMEM_DYN);
    cudaFuncSetAttribute(gemm2_mm, cudaFuncAttributeMaxDynamicSharedMemorySize, SMEM_DYN);

    extract_all<<<dim3(BATCH, 3), 256>>>(x, l);
    mask_kernel<<<dim3((IMH * IMW / 4) / 256, BATCH), 256>>>(l, out + BATCH * NOUT);
    lout_kernel<<<(BATCH * HLI) / 256, 256>>>(l, w2, b2);
    gemm1_mm<<<dim3(HGI / NT, KS1), GT, SMEM_DYN>>>(w1);
    reduce1_kernel<<<(BATCH * HGI / 4) / 256, 256>>>(b1);
    gemm2_mm<<<dim3(NOUT / NT, KS2), GT, SMEM_DYN>>>(w3, w4);
    reduce2_kernel<<<(BATCH * NOUT / 4) / 256, 256>>>(b3, b4, out);
}

// round 6
// speedup vs baseline: 2.6357x; 1.0734x over previous
#include <cuda_runtime.h>
#include <cuda_bf16.h>

// ---------------- problem constants ----------------
#define BATCH 128
#define CCH   3
#define IMH   224
#define IMW   224
#define GG    32
#define HGI   1024
#define HLI   256
#define DIN   9216
#define NOUT  1280

// ---------------- GEMM (mma.sync bf16x3) config ----------------
#define NT    64              // N tile per CTA
#define KSTG  32              // K per stage
#define GT    256             // threads (8 warps: 4 m x 2 n)
#define KS1   18
#define KSLICE1 (DIN / KS1)    // 512
#define NCH1  (KSLICE1 / KSTG) // 16
#define KS2   10              // 8 slices of w3 (128 each) + 2 of w4

// SMEM stage layout (bf16, row stride 40 elems = 80 bytes)
#define RS      80
#define OFF_AHI 0
#define OFF_ALO 10240
#define OFF_WHI 20480
#define OFF_WLO 25600
#define STG_BYTES 30720
#define SMEM_DYN (2 * STG_BYTES)   // 61440 (2 CTAs/SM fit: 122880 < 228K)

// ---------------- scratch ----------------
__device__ float g_phi  [BATCH * DIN];
__device__ float g_part1[KS1 * BATCH * HGI];
__device__ float g_s1   [BATCH * HGI];
__device__ float g_lout [BATCH * HLI];
__device__ float g_part2[KS2 * BATCH * NOUT];

// ---------------- PTX helpers (base-target only) ----------------
__device__ __forceinline__ unsigned smem_u32(const void* p) {
    unsigned a;
    asm("{ .reg .u64 t; cvta.to.shared.u64 t, %1; cvt.u32.u64 %0, t; }" : "=r"(a) : "l"(p));
    return a;
}
__device__ __forceinline__ void ldsm_x4(unsigned& r0, unsigned& r1, unsigned& r2,
                                        unsigned& r3, unsigned addr) {
    asm volatile("ldmatrix.sync.aligned.m8n8.x4.shared.b16 {%0,%1,%2,%3}, [%4];"
                 : "=r"(r0), "=r"(r1), "=r"(r2), "=r"(r3) : "r"(addr));
}
__device__ __forceinline__ void mma_bf16(float* c, const unsigned* a, const unsigned* b) {
    asm volatile("mma.sync.aligned.m16n8k16.row.col.f32.bf16.bf16.f32 "
                 "{%0,%1,%2,%3}, {%4,%5,%6,%7}, {%8,%9}, {%0,%1,%2,%3};"
                 : "+f"(c[0]), "+f"(c[1]), "+f"(c[2]), "+f"(c[3])
                 : "r"(a[0]), "r"(a[1]), "r"(a[2]), "r"(a[3]), "r"(b[0]), "r"(b[1]));
}

// fp32 -> bf16 hi + bf16 residual (lo), 4 at a time
__device__ __forceinline__ void cvt4(float4 v, uint2& hi, uint2& lo) {
    __nv_bfloat162 h0 = __floats2bfloat162_rn(v.x, v.y);
    __nv_bfloat162 h1 = __floats2bfloat162_rn(v.z, v.w);
    float r0 = v.x - __bfloat162float(h0.x);
    float r1 = v.y - __bfloat162float(h0.y);
    float r2 = v.z - __bfloat162float(h1.x);
    float r3 = v.w - __bfloat162float(h1.y);
    __nv_bfloat162 l0 = __floats2bfloat162_rn(r0, r1);
    __nv_bfloat162 l1 = __floats2bfloat162_rn(r2, r3);
    hi = make_uint2(*(unsigned*)&h0, *(unsigned*)&h1);
    lo = make_uint2(*(unsigned*)&l0, *(unsigned*)&l1);
}

// ---------------- split-K bf16x3 mma.sync GEMM body ----------------
__device__ __forceinline__ void gemm_body(const float* __restrict__ A, int ldA,
                                          const float* __restrict__ W, int ldW,
                                          float* __restrict__ outP, int ldOut,
                                          int bn, int kbeg, int nch) {
    extern __shared__ char smem[];
    const unsigned sb = smem_u32(smem);
    const int tid  = threadIdx.x;
    const int wid  = tid >> 5;
    const int lane = tid & 31;
    const int wm = (wid & 3) * 32;
    const int wn = (wid >> 2) * 32;

    float4 pa[4];
    float4 pw[2];

    auto ldg_stage = [&](int c) {
        const float* Ab = A + kbeg + c * KSTG;
#pragma unroll
        for (int j = 0; j < 4; j++) {
            int f4 = j * 256 + tid;
            pa[j] = *(const float4*)(Ab + (size_t)(f4 >> 3) * ldA + (f4 & 7) * 4);
        }
        const float* Wb = W + (size_t)bn * ldW + kbeg + c * KSTG;
#pragma unroll
        for (int j = 0; j < 2; j++) {
            int f4 = j * 256 + tid;
            pw[j] = *(const float4*)(Wb + (size_t)(f4 >> 3) * ldW + (f4 & 7) * 4);
        }
    };

    auto sts_stage = [&](int s) {
        char* st = smem + s * STG_BYTES;
#pragma unroll
        for (int j = 0; j < 4; j++) {
            int f4 = j * 256 + tid;
            int off = (f4 >> 3) * RS + (f4 & 7) * 8;
            uint2 hi, lo;
            cvt4(pa[j], hi, lo);
            *(uint2*)(st + OFF_AHI + off) = hi;
            *(uint2*)(st + OFF_ALO + off) = lo;
        }
#pragma unroll
        for (int j = 0; j < 2; j++) {
            int f4 = j * 256 + tid;
            int off = (f4 >> 3) * RS + (f4 & 7) * 8;
            uint2 hi, lo;
            cvt4(pw[j], hi, lo);
            *(uint2*)(st + OFF_WHI + off) = hi;
            *(uint2*)(st + OFF_WLO + off) = lo;
        }
    };

    float acc[2][4][4];
#pragma unroll
    for (int i = 0; i < 2; i++)
#pragma unroll
        for (int j = 0; j < 4; j++)
#pragma unroll
            for (int k = 0; k < 4; k++) acc[i][j][k] = 0.0f;

    ldg_stage(0);
    sts_stage(0);
    if (nch > 1) ldg_stage(1);
    __syncthreads();

    for (int c = 0; c < nch; c++) {
        const unsigned base = sb + (unsigned)(c & 1) * STG_BYTES;
#pragma unroll
        for (int kk = 0; kk < KSTG; kk += 16) {
            unsigned ahi[2][4], alo[2][4], bhi[4][2], blo[4][2];
#pragma unroll
            for (int mb = 0; mb < 2; mb++) {
                unsigned r = wm + mb * 16 + (lane & 15);
                unsigned ko = kk + ((lane & 16) ? 8 : 0);
                unsigned ad = base + r * RS + ko * 2;
                ldsm_x4(ahi[mb][0], ahi[mb][1], ahi[mb][2], ahi[mb][3], ad + OFF_AHI);
                ldsm_x4(alo[mb][0], alo[mb][1], alo[mb][2], alo[mb][3], ad + OFF_ALO);
            }
#pragma unroll
            for (int p = 0; p < 2; p++) {
                unsigned m = lane >> 3;
                unsigned r = wn + p * 16 + ((m >= 2) ? 8 : 0) + (lane & 7);
                unsigned ko = kk + ((m & 1) ? 8 : 0);
                unsigned ad = base + r * RS + ko * 2;
                ldsm_x4(bhi[p * 2][0], bhi[p * 2][1], bhi[p * 2 + 1][0], bhi[p * 2 + 1][1],
                        ad + OFF_WHI);
                ldsm_x4(blo[p * 2][0], blo[p * 2][1], blo[p * 2 + 1][0], blo[p * 2 + 1][1],
                        ad + OFF_WLO);
            }
#pragma unroll
            for (int mb = 0; mb < 2; mb++)
#pragma unroll
                for (int nb = 0; nb < 4; nb++) {
                    mma_bf16(acc[mb][nb], ahi[mb], bhi[nb]);
                    mma_bf16(acc[mb][nb], ahi[mb], blo[nb]);
                    mma_bf16(acc[mb][nb], alo[mb], bhi[nb]);
                }
        }
        if (c + 1 < nch) {
            sts_stage((c + 1) & 1);
            if (c + 2 < nch) ldg_stage(c + 2);
            __syncthreads();
        }
    }

#pragma unroll
    for (int mb = 0; mb < 2; mb++) {
        const int row = wm + mb * 16 + (lane >> 2);
#pragma unroll
        for (int nb = 0; nb < 4; nb++) {
            const int col = bn + wn + nb * 8 + (lane & 3) * 2;
            float* o = outP + (size_t)row * ldOut + col;
            *(float2*)o = make_float2(acc[mb][nb][0], acc[mb][nb][1]);
            *(float2*)(o + 8 * (size_t)ldOut) = make_float2(acc[mb][nb][2], acc[mb][nb][3]);
        }
    }
}

__global__ void __launch_bounds__(GT, 2) gemm1_mm(const float* __restrict__ w1) {
    gemm_body(g_phi, DIN, w1, DIN,
              g_part1 + (size_t)blockIdx.y * BATCH * HGI, HGI,
              blockIdx.x * NT, blockIdx.y * KSLICE1, NCH1);
}

__global__ void __launch_bounds__(GT, 2) gemm2_mm(const float* __restrict__ w3,
                                                  const float* __restrict__ w4) {
    const int z = blockIdx.y;
    const float* A; const float* W; int ld, kb;
    if (z < 8) { A = g_s1;   W = w3; ld = HGI; kb = z * 128; }
    else       { A = g_lout; W = w4; ld = HLI; kb = (z - 8) * 128; }
    gemm_body(A, ld, W, ld,
              g_part2 + (size_t)z * BATCH * NOUT, NOUT,
              blockIdx.x * NT, kb, 128 / KSTG);
}

// ---------------- glimpse start index ----------------
__device__ __forceinline__ int start_idx(float lv) {
    return (int)(0.5f * ((lv + 1.0f) * 224.0f));
}

// ---------------- fused prologue: mask + extract + lout ----------------
#define MASK_BLKS (BATCH * 49)             // 6272 (49 * 256 * 4 floats = 50176 px)
#define EXT_BLKS  (BATCH * 3)              // 384
#define LOUT_BLKS (BATCH * HLI / 256)      // 128
#define PRO_BLKS  (MASK_BLKS + EXT_BLKS + LOUT_BLKS)

template <int SCALE>
__device__ __forceinline__ void extract_body(const float* __restrict__ x,
                                             const float* __restrict__ l, int b) {
    constexpr int F   = 1 << SCALE;
    constexpr int PAD = (GG << SCALE) >> 1;
    const int sx = start_idx(l[b * 2 + 0]);
    const int sy = start_idx(l[b * 2 + 1]);
    const float* xb = x + (size_t)b * CCH * IMH * IMW;
    const float invf = 1.0f / (float)(F * F);

    for (int idx = threadIdx.x; idx < CCH * GG * GG; idx += blockDim.x) {
        const int col = idx & 31;
        const int r   = (idx >> 5) & 31;
        const int c   = idx >> 10;
        const int row0 = sy - PAD + r * F;
        const int col0 = sx - PAD + col * F;
        float s = 0.0f;
#pragma unroll
        for (int dy = 0; dy < F; dy++) {
            const int rr = row0 + dy;
            if (rr < 0 || rr >= IMH) continue;
            const float* xr = xb + ((size_t)c * IMH + rr) * IMW;
#pragma unroll
            for (int dx = 0; dx < F; dx++) {
                const int cc = col0 + dx;
                if (cc >= 0 && cc < IMW) s += xr[cc];
            }
        }
        g_phi[(size_t)b * DIN + ((SCALE * CCH + c) * GG + r) * GG + col] = s * invf;
    }
}

__global__ void prologue_kernel(const float* __restrict__ x,
                                const float* __restrict__ l,
                                const float* __restrict__ w2,
                                const float* __restrict__ b2,
                                float* __restrict__ om) {
    const int bid = blockIdx.x;
    if (bid < MASK_BLKS) {
        const int b = bid / 49;
        const int q = (bid - b * 49) * 256 + threadIdx.x;   // float4 index < 12544
        const int sx = start_idx(l[b * 2 + 0]);
        const int sy = start_idx(l[b * 2 + 1]);
        const int r  = q / 56;
        const int c0 = (q - r * 56) * 4;
        const bool iny = (r >= sy - 64) && (r < sy + 64);
        float4 v;
        v.x = (iny && c0 + 0 >= sx - 64 && c0 + 0 < sx + 64) ? 1.0f : 0.0f;
        v.y = (iny && c0 + 1 >= sx - 64 && c0 + 1 < sx + 64) ? 1.0f : 0.0f;
        v.z = (iny && c0 + 2 >= sx - 64 && c0 + 2 < sx + 64) ? 1.0f : 0.0f;
        v.w = (iny && c0 + 3 >= sx - 64 && c0 + 3 < sx + 64) ? 1.0f : 0.0f;
        ((float4*)(om + (size_t)b * IMH * IMW))[q] = v;
    } else if (bid < MASK_BLKS + EXT_BLKS) {
        const int e = bid - MASK_BLKS;
        const int b = e & 127;
        switch (e >> 7) {
            case 0: extract_body<0>(x, l, b); break;
            case 1: extract_body<1>(x, l, b); break;
            default: extract_body<2>(x, l, b); break;
        }
    } else {
        const int i = (bid - MASK_BLKS - EXT_BLKS) * 256 + threadIdx.x;
        const int m = i >> 8;
        const int j = i & 255;
        float v = fmaf(l[m * 2 + 0], w2[j * 2 + 0],
                  fmaf(l[m * 2 + 1], w2[j * 2 + 1], b2[j]));
        g_lout[i] = fmaxf(v, 0.0f);
    }
}

// ---------------- reductions (bias + relu), float4 ----------------
__global__ void reduce1_kernel(const float* __restrict__ b1) {
    const int i4 = blockIdx.x * blockDim.x + threadIdx.x;  // < 32768
    float4 s = ((const float4*)g_part1)[i4];
#pragma unroll
    for (int p = 1; p < KS1; p++) {
        float4 v = ((const float4*)(g_part1 + (size_t)p * BATCH * HGI))[i4];
        s.x += v.x; s.y += v.y; s.z += v.z; s.w += v.w;
    }
    float4 bb = ((const float4*)b1)[i4 & 255];
    s.x = fmaxf(s.x + bb.x, 0.0f); s.y = fmaxf(s.y + bb.y, 0.0f);
    s.z = fmaxf(s.z + bb.z, 0.0f); s.w = fmaxf(s.w + bb.w, 0.0f);
    ((float4*)g_s1)[i4] = s;
}

__global__ void reduce2_kernel(const float* __restrict__ b3,
                               const float* __restrict__ b4,
                               float* __restrict__ out) {
    const int i4 = blockIdx.x * blockDim.x + threadIdx.x;  // < 40960
    float4 s = ((const float4*)g_part2)[i4];
#pragma unroll
    for (int p = 1; p < KS2; p++) {
        float4 v = ((const float4*)(g_part2 + (size_t)p * BATCH * NOUT))[i4];
        s.x += v.x; s.y += v.y; s.z += v.z; s.w += v.w;
    }
    const int n4 = i4 % (NOUT / 4);
    float4 t3 = ((const float4*)b3)[n4];
    float4 t4 = ((const float4*)b4)[n4];
    s.x = fmaxf(s.x + t3.x + t4.x, 0.0f); s.y = fmaxf(s.y + t3.y + t4.y, 0.0f);
    s.z = fmaxf(s.z + t3.z + t4.z, 0.0f); s.w = fmaxf(s.w + t3.w + t4.w, 0.0f);
    ((float4*)out)[i4] = s;
}

// ---------------- launch ----------------
extern "C" void kernel_launch(void* const* d_in, const int* in_sizes, int n_in,
                              void* d_out, int out_size) {
    const float* x  = (const float*)d_in[0];
    const float* l  = (const float*)d_in[1];
    const float* w1 = (const float*)d_in[2];
    const float* b1 = (const float*)d_in[3];
    const float* w2 = (const float*)d_in[4];
    const float* b2 = (const float*)d_in[5];
    const float* w3 = (const float*)d_in[6];
    const float* b3 = (const float*)d_in[7];
    const float* w4 = (const float*)d_in[8];
    const float* b4 = (const float*)d_in[9];
    float* out = (float*)d_out;

    cudaFuncSetAttribute(gemm1_mm, cudaFuncAttributeMaxDynamicSharedMemorySize, SMEM_DYN);
    cudaFuncSetAttribute(gemm2_mm, cudaFuncAttributeMaxDynamicSharedMemorySize, SMEM_DYN);

    prologue_kernel<<<PRO_BLKS, 256>>>(x, l, w2, b2, out + BATCH * NOUT);
    gemm1_mm<<<dim3(HGI / NT, KS1), GT, SMEM_DYN>>>(w1);
    reduce1_kernel<<<(BATCH * HGI / 4) / 256, 256>>>(b1);
    gemm2_mm<<<dim3(NOUT / NT, KS2), GT, SMEM_DYN>>>(w3, w4);
    reduce2_kernel<<<(BATCH * NOUT / 4) / 256, 256>>>(b3, b4, out);
}